// round 10
// baseline (speedup 1.0000x reference)
#include <cuda_runtime.h>

#define NPTS    2048
#define THREADS 224                // 7 warps
#define GRPS    7
#define NI      8                  // 8 independent i-chains per thread
#define IPB     (GRPS*NI)          // 56 i's per CTA -> 37 x 4 = 148 CTAs (1/SM exact)
#define EPS     1e-5f
#define BIAS    1e-5f              // sq bias: absorbs dot-form cancellation (diagonal-safe)

__global__ __launch_bounds__(THREADS, 1) void spring_kernel(
    const float* __restrict__ X, const float* __restrict__ Kp,
    const float* __restrict__ Bp, float* __restrict__ out)
{
    __shared__ float4 xs[NPTS];
    __shared__ float4 red[GRPS];
    const int b   = blockIdx.y;
    const int tid = threadIdx.x;
    const float* Xb = X + (size_t)b * NPTS * 3;

    // Stage batch into SMEM as (x, y, z, |p|^2) + partial sums for S = sum_j x_j.
    float sx = 0.f, sy = 0.f, sz = 0.f;
    for (int p = tid; p < NPTS; p += THREADS) {
        const float x = Xb[3*p], y = Xb[3*p+1], z = Xb[3*p+2];
        xs[p] = make_float4(x, y, z, fmaf(x, x, fmaf(y, y, z*z)));
        sx += x; sy += y; sz += z;
    }
    #pragma unroll
    for (int m = 16; m >= 1; m >>= 1) {
        sx += __shfl_xor_sync(0xffffffffu, sx, m);
        sy += __shfl_xor_sync(0xffffffffu, sy, m);
        sz += __shfl_xor_sync(0xffffffffu, sz, m);
    }
    if ((tid & 31) == 0) red[tid >> 5] = make_float4(sx, sy, sz, 0.f);
    __syncthreads();
    float4 S = make_float4(0.f, 0.f, 0.f, 0.f);
    #pragma unroll
    for (int wdx = 0; wdx < GRPS; wdx++) {
        S.x += red[wdx].x; S.y += red[wdx].y; S.z += red[wdx].z;
    }

    const float K = *Kp;
    const float c = K * (*Bp + EPS);   // f = K - c*w,  w ~= rsqrt(sq)

    const int grp   = tid >> 5;        // warp id, 0..6
    const int slice = tid & 31;        // lane
    const int ib = blockIdx.x * IPB + grp;

    // 8 i's per thread, GRPS apart (clamped; spares recompute i=2047, store-guarded).
    float m2x[NI], m2y[NI], m2z[NI], base[NI];
    float sr[NI], hpx[NI], hpy[NI], hpz[NI];
    #pragma unroll
    for (int q = 0; q < NI; q++) {
        int i = ib + q * GRPS; if (i > NPTS - 1) i = NPTS - 1;
        const float4 v = xs[i];
        m2x[q] = -2.f * v.x; m2y[q] = -2.f * v.y; m2z[q] = -2.f * v.z;
        base[q] = v.w + BIAS;
        sr[q] = 0.f; hpx[q] = 0.f; hpy[q] = 0.f; hpz[q] = 0.f;
    }

    // 32 lanes read 32 consecutive float4s: conflict-free LDS.128.
    // One load feeds 8 independent chains:
    //   sq = (|pi|^2 + bias - 2 pi.pj) + |pj|^2
    //   h  = (sum r)*pi - sum(r*pj)
    #pragma unroll 2
    for (int j = slice; j < NPTS; j += 32) {
        const float4 pj = xs[j];
        #pragma unroll
        for (int q = 0; q < NI; q++) {
            float t = fmaf(m2x[q], pj.x, base[q]);
            const float u = fmaf(m2y[q], pj.y, pj.w);
            t = fmaf(m2z[q], pj.z, t);
            const float r = rsqrtf(t + u);
            sr[q] += r;
            hpx[q] = fmaf(r, pj.x, hpx[q]);
            hpy[q] = fmaf(r, pj.y, hpy[q]);
            hpz[q] = fmaf(r, pj.z, hpz[q]);
        }
    }

    // Warp reduction over the 32 j-slices.
    #pragma unroll
    for (int m = 1; m < 32; m <<= 1) {
        #pragma unroll
        for (int q = 0; q < NI; q++) {
            sr[q]  += __shfl_xor_sync(0xffffffffu, sr[q],  m);
            hpx[q] += __shfl_xor_sync(0xffffffffu, hpx[q], m);
            hpy[q] += __shfl_xor_sync(0xffffffffu, hpy[q], m);
            hpz[q] += __shfl_xor_sync(0xffffffffu, hpz[q], m);
        }
    }

    if (slice == 0) {
        #pragma unroll
        for (int q = 0; q < NI; q++) {
            const int i = ib + q * GRPS;
            if (i < NPTS) {
                const float4 v = xs[i];   // reload pi (kept out of loop-live regs)
                const float hxv = fmaf(sr[q], v.x, -hpx[q]);
                const float hyv = fmaf(sr[q], v.y, -hpy[q]);
                const float hzv = fmaf(sr[q], v.z, -hpz[q]);
                float* o = out + ((size_t)b * NPTS + i) * 3;
                o[0] = fmaf(K, fmaf((float)NPTS, v.x, -S.x), fmaf(-c, hxv, v.x));
                o[1] = fmaf(K, fmaf((float)NPTS, v.y, -S.y), fmaf(-c, hyv, v.y));
                o[2] = fmaf(K, fmaf((float)NPTS, v.z, -S.z), fmaf(-c, hzv, v.z));
            }
        }
    }
}

extern "C" void kernel_launch(void* const* d_in, const int* in_sizes, int n_in,
                              void* d_out, int out_size) {
    const float* X = (const float*)d_in[0];
    const float* K = (const float*)d_in[1];
    const float* B = (const float*)d_in[2];
    float* out = (float*)d_out;

    const int batch = in_sizes[0] / (NPTS * 3);
    dim3 grid((NPTS + IPB - 1) / IPB, batch);   // 37 x 4 = 148 CTAs
    spring_kernel<<<grid, THREADS>>>(X, K, B, out);
}

// round 11
// speedup vs baseline: 1.0886x; 1.0886x over previous
#include <cuda_runtime.h>

#define NPTS    2048
#define THREADS 256
#define SLICES  32                 // j-slices per i (full warp)
#define GRPS    (THREADS/SLICES)   // 8 warps per CTA
#define NI      4                  // i's per thread (optimal ILP per R8/R10)
#define IPB     (GRPS*NI)          // 32 i's per CTA -> 64 x 4 = 256 CTAs
#define EPS     1e-5f
#define BIAS    1e-5f              // sq bias: absorbs dot-form cancellation (diagonal-safe)

__global__ __launch_bounds__(THREADS, 2) void spring_kernel(
    const float* __restrict__ X, const float* __restrict__ Kp,
    const float* __restrict__ Bp, float* __restrict__ out)
{
    __shared__ float4 xs[NPTS];
    __shared__ float4 red[GRPS];
    const int b   = blockIdx.y;
    const int tid = threadIdx.x;
    const float* Xb = X + (size_t)b * NPTS * 3;

    // Stage batch into SMEM as (x, y, z, |p|^2) + partial sums for S = sum_j x_j.
    float sx = 0.f, sy = 0.f, sz = 0.f;
    for (int p = tid; p < NPTS; p += THREADS) {
        const float x = Xb[3*p], y = Xb[3*p+1], z = Xb[3*p+2];
        xs[p] = make_float4(x, y, z, fmaf(x, x, fmaf(y, y, z*z)));
        sx += x; sy += y; sz += z;
    }
    #pragma unroll
    for (int m = 16; m >= 1; m >>= 1) {
        sx += __shfl_xor_sync(0xffffffffu, sx, m);
        sy += __shfl_xor_sync(0xffffffffu, sy, m);
        sz += __shfl_xor_sync(0xffffffffu, sz, m);
    }
    if ((tid & 31) == 0) red[tid >> 5] = make_float4(sx, sy, sz, 0.f);
    __syncthreads();
    float4 S = make_float4(0.f, 0.f, 0.f, 0.f);
    #pragma unroll
    for (int wdx = 0; wdx < GRPS; wdx++) {
        S.x += red[wdx].x; S.y += red[wdx].y; S.z += red[wdx].z;
    }

    const float K = *Kp;
    const float c = K * (*Bp + EPS);   // f = K - c*w,  w ~= rsqrt(sq)

    const int grp   = tid >> 5;        // warp id, 0..7
    const int slice = tid & 31;        // lane
    const int ib = blockIdx.x * IPB + grp;

    // 4 i's per thread, GRPS apart.
    float m2x[NI], m2y[NI], m2z[NI], base[NI];
    float sr[NI], hpx[NI], hpy[NI], hpz[NI];
    #pragma unroll
    for (int q = 0; q < NI; q++) {
        const float4 v = xs[ib + q * GRPS];
        m2x[q] = -2.f * v.x; m2y[q] = -2.f * v.y; m2z[q] = -2.f * v.z;
        base[q] = v.w + BIAS;
        sr[q] = 0.f; hpx[q] = 0.f; hpy[q] = 0.f; hpz[q] = 0.f;
    }

    // 32 lanes read 32 consecutive float4s: conflict-free LDS.128.
    // Dot-product body (9 slots/pair):
    //   sq = (|pi|^2 + bias - 2 pi.pj) + |pj|^2
    //   h  = (sum r)*pi - sum(r*pj)
    #pragma unroll 8
    for (int j = slice; j < NPTS; j += SLICES) {
        const float4 pj = xs[j];
        #pragma unroll
        for (int q = 0; q < NI; q++) {
            float t = fmaf(m2x[q], pj.x, base[q]);
            const float u = fmaf(m2y[q], pj.y, pj.w);
            t = fmaf(m2z[q], pj.z, t);
            const float r = rsqrtf(t + u);
            sr[q] += r;
            hpx[q] = fmaf(r, pj.x, hpx[q]);
            hpy[q] = fmaf(r, pj.y, hpy[q]);
            hpz[q] = fmaf(r, pj.z, hpz[q]);
        }
    }

    // Warp reduction over the 32 j-slices.
    #pragma unroll
    for (int m = 1; m < 32; m <<= 1) {
        #pragma unroll
        for (int q = 0; q < NI; q++) {
            sr[q]  += __shfl_xor_sync(0xffffffffu, sr[q],  m);
            hpx[q] += __shfl_xor_sync(0xffffffffu, hpx[q], m);
            hpy[q] += __shfl_xor_sync(0xffffffffu, hpy[q], m);
            hpz[q] += __shfl_xor_sync(0xffffffffu, hpz[q], m);
        }
    }

    if (slice == 0) {
        #pragma unroll
        for (int q = 0; q < NI; q++) {
            const int i = ib + q * GRPS;
            const float4 v = xs[i];     // reload pi (kept out of loop-live regs)
            const float hxv = fmaf(sr[q], v.x, -hpx[q]);
            const float hyv = fmaf(sr[q], v.y, -hpy[q]);
            const float hzv = fmaf(sr[q], v.z, -hpz[q]);
            float* o = out + ((size_t)b * NPTS + i) * 3;
            o[0] = fmaf(K, fmaf((float)NPTS, v.x, -S.x), fmaf(-c, hxv, v.x));
            o[1] = fmaf(K, fmaf((float)NPTS, v.y, -S.y), fmaf(-c, hyv, v.y));
            o[2] = fmaf(K, fmaf((float)NPTS, v.z, -S.z), fmaf(-c, hzv, v.z));
        }
    }
}

extern "C" void kernel_launch(void* const* d_in, const int* in_sizes, int n_in,
                              void* d_out, int out_size) {
    const float* X = (const float*)d_in[0];
    const float* K = (const float*)d_in[1];
    const float* B = (const float*)d_in[2];
    float* out = (float*)d_out;

    const int batch = in_sizes[0] / (NPTS * 3);
    dim3 grid(NPTS / IPB, batch);   // 64 x 4 = 256 CTAs
    spring_kernel<<<grid, THREADS>>>(X, K, B, out);
}